// round 1
// baseline (speedup 1.0000x reference)
#include <cuda_runtime.h>
#include <cstdint>
#include <math_constants.h>

// Problem shape (fixed for this problem id): M=8192, N=4096, K=4096
#define MAX_N 4096
#define MAX_M 8192
#define MAX_K 4096

// Scratch (allocation-free per harness rules)
__device__ int8_t  g_Wq[(size_t)MAX_N * MAX_K];   // 16 MB, [N][K]
__device__ uint8_t g_Xq[(size_t)MAX_M * MAX_K];   // 32 MB, [M][K]
__device__ float   g_wscale[MAX_N];
__device__ int     g_wrowsum[MAX_N];
__device__ float   g_ascale[MAX_M];
__device__ int     g_azp[MAX_M];

__device__ __forceinline__ int dp4a_us(unsigned a, int b, int c) {
    int d;
    asm("dp4a.u32.s32 %0, %1, %2, %3;" : "=r"(d) : "r"(a), "r"(b), "r"(c));
    return d;
}

// ---------------- Weight quantization: one block per output row n ----------------
__global__ void wq_kernel(const float* __restrict__ W, int K) {
    __shared__ float sredf[256];
    __shared__ int   sredi[256];
    __shared__ float sscale;
    const int n = blockIdx.x;
    const float* row = W + (size_t)n * K;

    float amax = 0.f;
    for (int k = threadIdx.x; k < K; k += 256)
        amax = fmaxf(amax, fabsf(row[k]));
    sredf[threadIdx.x] = amax;
    __syncthreads();
    for (int s = 128; s > 0; s >>= 1) {
        if (threadIdx.x < s) sredf[threadIdx.x] = fmaxf(sredf[threadIdx.x], sredf[threadIdx.x + s]);
        __syncthreads();
    }
    if (threadIdx.x == 0) {
        float a = sredf[0];
        sscale = (a > 0.f) ? a / 127.0f : 1.0f;
    }
    __syncthreads();
    const float scale = sscale;

    int sum = 0;
    int8_t* outq = g_Wq + (size_t)n * K;
    for (int k = threadIdx.x; k < K; k += 256) {
        float q = rintf(row[k] / scale);
        q = fminf(fmaxf(q, -127.f), 127.f);
        int qi = (int)q;
        outq[k] = (int8_t)qi;
        sum += qi;
    }
    sredi[threadIdx.x] = sum;
    __syncthreads();
    for (int s = 128; s > 0; s >>= 1) {
        if (threadIdx.x < s) sredi[threadIdx.x] += sredi[threadIdx.x + s];
        __syncthreads();
    }
    if (threadIdx.x == 0) {
        g_wscale[n]  = scale;
        g_wrowsum[n] = sredi[0];
    }
}

// ---------------- Activation quantization: one block per token m ----------------
__global__ void xq_kernel(const float* __restrict__ X, int K) {
    __shared__ float smin[256], smax[256];
    __shared__ float sscale;
    __shared__ float szp;
    const int m = blockIdx.x;
    const float* row = X + (size_t)m * K;

    float vmin = CUDART_INF_F, vmax = -CUDART_INF_F;
    for (int k = threadIdx.x; k < K; k += 256) {
        float v = row[k];
        vmin = fminf(vmin, v);
        vmax = fmaxf(vmax, v);
    }
    smin[threadIdx.x] = vmin;
    smax[threadIdx.x] = vmax;
    __syncthreads();
    for (int s = 128; s > 0; s >>= 1) {
        if (threadIdx.x < s) {
            smin[threadIdx.x] = fminf(smin[threadIdx.x], smin[threadIdx.x + s]);
            smax[threadIdx.x] = fmaxf(smax[threadIdx.x], smax[threadIdx.x + s]);
        }
        __syncthreads();
    }
    if (threadIdx.x == 0) {
        float lo = smin[0], hi = smax[0];
        float rng = hi - lo;
        float scale = (rng > 0.f) ? rng / 255.0f : 1.0f;
        sscale = scale;
        szp = rintf(-lo / scale);
    }
    __syncthreads();
    const float scale = sscale;
    const float zp = szp;

    uint8_t* outq = g_Xq + (size_t)m * K;
    for (int k = threadIdx.x; k < K; k += 256) {
        float q = rintf(row[k] / scale) + zp;
        q = fminf(fmaxf(q, 0.f), 255.f);
        outq[k] = (uint8_t)(int)q;
    }
    if (threadIdx.x == 0) {
        g_ascale[m] = scale;
        g_azp[m]    = (int)zp;
    }
}

// ---------------- int8 GEMM: C[m][n] = dot(Xq[m,:], Wq[n,:]) ----------------
// 128x128 tile, BK = 64 bytes (16 int32 words), 256 threads, 8x8 outputs/thread.
__global__ __launch_bounds__(256) void gemm_kernel(
    const float* __restrict__ bias,
    float* __restrict__ out,
    int M, int N, int Kw /* K/4 int32 words per row */)
{
    __shared__ int As[16][128];
    __shared__ int Bs[16][128];

    const int tid = threadIdx.x;
    const int tx = tid & 15;       // 0..15 -> n direction
    const int ty = tid >> 4;       // 0..15 -> m direction
    const int m0 = blockIdx.y * 128;
    const int n0 = blockIdx.x * 128;

    const int* __restrict__ Aw = (const int*)g_Xq;  // [M][Kw]
    const int* __restrict__ Bw = (const int*)g_Wq;  // [N][Kw]

    int acc[8][8];
#pragma unroll
    for (int i = 0; i < 8; i++)
#pragma unroll
        for (int j = 0; j < 8; j++) acc[i][j] = 0;

    for (int k0 = 0; k0 < Kw; k0 += 16) {
        // Load tiles: 128 rows x 16 words each, as int4 (512 int4 per tile, 2 per thread)
#pragma unroll
        for (int it = 0; it < 2; it++) {
            int i   = tid + it * 256;
            int row = i >> 2;
            int grp = i & 3;
            int4 va = *(const int4*)(Aw + (size_t)(m0 + row) * Kw + k0 + grp * 4);
            As[grp * 4 + 0][row] = va.x;
            As[grp * 4 + 1][row] = va.y;
            As[grp * 4 + 2][row] = va.z;
            As[grp * 4 + 3][row] = va.w;
            int4 vb = *(const int4*)(Bw + (size_t)(n0 + row) * Kw + k0 + grp * 4);
            Bs[grp * 4 + 0][row] = vb.x;
            Bs[grp * 4 + 1][row] = vb.y;
            Bs[grp * 4 + 2][row] = vb.z;
            Bs[grp * 4 + 3][row] = vb.w;
        }
        __syncthreads();

#pragma unroll
        for (int kk = 0; kk < 16; kk++) {
            int a[8], b[8];
            *(int4*)&a[0] = *(const int4*)&As[kk][ty * 8];
            *(int4*)&a[4] = *(const int4*)&As[kk][ty * 8 + 4];
            *(int4*)&b[0] = *(const int4*)&Bs[kk][tx * 8];
            *(int4*)&b[4] = *(const int4*)&Bs[kk][tx * 8 + 4];
#pragma unroll
            for (int i = 0; i < 8; i++)
#pragma unroll
                for (int j = 0; j < 8; j++)
                    acc[i][j] = dp4a_us((unsigned)a[i], b[j], acc[i][j]);
        }
        __syncthreads();
    }

    // Epilogue: Y = (acc - zp[m]*rowsum[n]) * (sa[m]*sw[n]) + bias[n]
    const int m_base = m0 + ty * 8;
    const int n_base = n0 + tx * 8;
    float sw[8]; int rs[8]; float bi[8];
#pragma unroll
    for (int j = 0; j < 8; j++) {
        sw[j] = g_wscale[n_base + j];
        rs[j] = g_wrowsum[n_base + j];
        bi[j] = bias[n_base + j];
    }
#pragma unroll
    for (int i = 0; i < 8; i++) {
        const int m = m_base + i;
        const float sa = g_ascale[m];
        const int   zp = g_azp[m];
        float v[8];
#pragma unroll
        for (int j = 0; j < 8; j++)
            v[j] = (float)(acc[i][j] - zp * rs[j]) * (sa * sw[j]) + bi[j];
        float4* dst = (float4*)(out + (size_t)m * N + n_base);
        dst[0] = make_float4(v[0], v[1], v[2], v[3]);
        dst[1] = make_float4(v[4], v[5], v[6], v[7]);
    }
}

extern "C" void kernel_launch(void* const* d_in, const int* in_sizes, int n_in,
                              void* d_out, int out_size) {
    const float* x    = (const float*)d_in[0];
    const float* w    = (const float*)d_in[1];
    const float* bias = (const float*)d_in[2];
    float* out = (float*)d_out;

    const int N = in_sizes[2];              // 4096
    const int K = in_sizes[1] / N;          // 4096
    const int M = in_sizes[0] / K;          // 8192

    wq_kernel<<<N, 256>>>(w, K);
    xq_kernel<<<M, 256>>>(x, K);

    dim3 grid(N / 128, M / 128);
    gemm_kernel<<<grid, 256>>>(bias, out, M, N, K / 4);
}

// round 6
// speedup vs baseline: 1.0885x; 1.0885x over previous
#include <cuda_runtime.h>
#include <cstdint>

#define K_DIM 4096
#define M_DIM 8192
#define N_DIM 4096

// GEMM tiling
#define BM 128
#define BN 128
#define BKB 64            // K bytes per mainloop iter
#define KIT (K_DIM / BKB) // 64
#define ROWSTR 80         // padded smem row stride (conflict-free ldmatrix)
#define TILE_BYTES (BM * ROWSTR)          // 10240
#define STAGE_BYTES (2 * TILE_BYTES)      // A + B per stage
#define NSTG 3
#define OFF_TAB (NSTG * STAGE_BYTES)      // 61440
#define SMEM_TOTAL (OFF_TAB + 128 * 12)   // + sw/rs/bi tables

// ---------------- scratch (allocation-free) ----------------
__device__ __align__(16) int8_t  g_Wq[(size_t)N_DIM * K_DIM];   // [N][K] row-major
__device__ __align__(16) uint8_t g_Xq[(size_t)M_DIM * K_DIM];   // [M][K] row-major
__device__ float g_wscale[N_DIM];
__device__ int   g_wrowsum[N_DIM];
__device__ float g_ascale[M_DIM];
__device__ int   g_azp[M_DIM];

// ---------------- PTX helpers (ALL base-target sm_103 safe) ----------------
__device__ __forceinline__ uint32_t smem_u32(const void* p) {
    uint32_t a;
    asm("{ .reg .u64 t; cvta.to.shared.u64 t, %1; cvt.u32.u64 %0, t; }" : "=r"(a) : "l"(p));
    return a;
}
__device__ __forceinline__ void cp_async16(uint32_t dst, const void* src) {
    asm volatile("cp.async.cg.shared.global [%0], [%1], 16;" :: "r"(dst), "l"(src));
}
#define CP_COMMIT() asm volatile("cp.async.commit_group;" ::: "memory")
#define CP_WAIT1()  asm volatile("cp.async.wait_group 1;" ::: "memory")

__device__ __forceinline__ void ldsm_x4(uint32_t addr, uint32_t& r0, uint32_t& r1,
                                        uint32_t& r2, uint32_t& r3) {
    asm volatile("ldmatrix.sync.aligned.m8n8.x4.shared.b16 {%0,%1,%2,%3}, [%4];"
                 : "=r"(r0), "=r"(r1), "=r"(r2), "=r"(r3) : "r"(addr));
}
__device__ __forceinline__ void mma_u8s8(int* c, const uint32_t* a, const uint32_t* b) {
    asm volatile("mma.sync.aligned.m16n8k32.row.col.s32.u8.s8.s32 "
                 "{%0,%1,%2,%3}, {%4,%5,%6,%7}, {%8,%9}, {%0,%1,%2,%3};"
                 : "+r"(c[0]), "+r"(c[1]), "+r"(c[2]), "+r"(c[3])
                 : "r"(a[0]), "r"(a[1]), "r"(a[2]), "r"(a[3]), "r"(b[0]), "r"(b[1]));
}

// ---------------- weight quantization: one block per output row n ----------------
__global__ __launch_bounds__(256) void wq_kernel(const float* __restrict__ W) {
    const int n = blockIdx.x;
    const int t = threadIdx.x, wid = t >> 5, lid = t & 31;
    const float* row = W + (size_t)n * K_DIM;

    float4 v[4];
#pragma unroll
    for (int i = 0; i < 4; i++) v[i] = *(const float4*)(row + t * 16 + i * 4);

    float amax = 0.f;
#pragma unroll
    for (int i = 0; i < 4; i++)
        amax = fmaxf(amax, fmaxf(fmaxf(fabsf(v[i].x), fabsf(v[i].y)),
                                 fmaxf(fabsf(v[i].z), fabsf(v[i].w))));
#pragma unroll
    for (int o = 16; o > 0; o >>= 1)
        amax = fmaxf(amax, __shfl_xor_sync(0xffffffffu, amax, o));

    __shared__ float smx[8];
    __shared__ int   ssum[8];
    if (lid == 0) smx[wid] = amax;
    __syncthreads();
    float gmax = smx[0];
#pragma unroll
    for (int i = 1; i < 8; i++) gmax = fmaxf(gmax, smx[i]);
    const float scale = (gmax > 0.f) ? gmax / 127.0f : 1.0f;

    int lsum = 0;
    uint32_t wds[4];
#pragma unroll
    for (int i = 0; i < 4; i++) {
        int i0 = (int)fminf(fmaxf(rintf(v[i].x / scale), -127.f), 127.f);
        int i1 = (int)fminf(fmaxf(rintf(v[i].y / scale), -127.f), 127.f);
        int i2 = (int)fminf(fmaxf(rintf(v[i].z / scale), -127.f), 127.f);
        int i3 = (int)fminf(fmaxf(rintf(v[i].w / scale), -127.f), 127.f);
        lsum += i0 + i1 + i2 + i3;
        wds[i] = (uint32_t)(i0 & 0xFF) | ((uint32_t)(i1 & 0xFF) << 8) |
                 ((uint32_t)(i2 & 0xFF) << 16) | ((uint32_t)(i3 & 0xFF) << 24);
    }
#pragma unroll
    for (int o = 16; o > 0; o >>= 1) lsum += __shfl_xor_sync(0xffffffffu, lsum, o);
    if (lid == 0) ssum[wid] = lsum;
    __syncthreads();
    if (t == 0) {
        int s = 0;
#pragma unroll
        for (int i = 0; i < 8; i++) s += ssum[i];
        g_wrowsum[n] = s;
        g_wscale[n]  = scale;
    }
    *(int4*)(g_Wq + (size_t)n * K_DIM + t * 16) = make_int4(wds[0], wds[1], wds[2], wds[3]);
}

// ---------------- activation quantization: one block per token m ----------------
__global__ __launch_bounds__(256) void xq_kernel(const float* __restrict__ X) {
    const int m = blockIdx.x;
    const int t = threadIdx.x, wid = t >> 5, lid = t & 31;
    const float* row = X + (size_t)m * K_DIM;

    float4 v[4];
#pragma unroll
    for (int i = 0; i < 4; i++) v[i] = *(const float4*)(row + t * 16 + i * 4);

    float lmin = v[0].x, lmax = v[0].x;
#pragma unroll
    for (int i = 0; i < 4; i++) {
        lmin = fminf(lmin, fminf(fminf(v[i].x, v[i].y), fminf(v[i].z, v[i].w)));
        lmax = fmaxf(lmax, fmaxf(fmaxf(v[i].x, v[i].y), fmaxf(v[i].z, v[i].w)));
    }
#pragma unroll
    for (int o = 16; o > 0; o >>= 1) {
        lmin = fminf(lmin, __shfl_xor_sync(0xffffffffu, lmin, o));
        lmax = fmaxf(lmax, __shfl_xor_sync(0xffffffffu, lmax, o));
    }
    __shared__ float smn[8], smx[8];
    if (lid == 0) { smn[wid] = lmin; smx[wid] = lmax; }
    __syncthreads();
    float gmin = smn[0], gmax = smx[0];
#pragma unroll
    for (int i = 1; i < 8; i++) { gmin = fminf(gmin, smn[i]); gmax = fmaxf(gmax, smx[i]); }

    const float rng   = gmax - gmin;
    const float scale = (rng > 0.f) ? rng / 255.0f : 1.0f;
    const float zp    = rintf(-gmin / scale);
    if (t == 0) { g_ascale[m] = scale; g_azp[m] = (int)zp; }

    uint32_t wds[4];
#pragma unroll
    for (int i = 0; i < 4; i++) {
        uint32_t q0 = (uint32_t)fminf(fmaxf(rintf(v[i].x / scale) + zp, 0.f), 255.f);
        uint32_t q1 = (uint32_t)fminf(fmaxf(rintf(v[i].y / scale) + zp, 0.f), 255.f);
        uint32_t q2 = (uint32_t)fminf(fmaxf(rintf(v[i].z / scale) + zp, 0.f), 255.f);
        uint32_t q3 = (uint32_t)fminf(fmaxf(rintf(v[i].w / scale) + zp, 0.f), 255.f);
        wds[i] = q0 | (q1 << 8) | (q2 << 16) | (q3 << 24);
    }
    *(int4*)(g_Xq + (size_t)m * K_DIM + t * 16) = make_int4(wds[0], wds[1], wds[2], wds[3]);
}

// ---------------- int8 tensor-core GEMM (mma.sync u8.s8) ----------------
// 128x128 tile, BK=64B, 3-stage cp.async pipeline, 8 warps (4m x 2n), warp tile 32x64.
__global__ __launch_bounds__(256, 1) void gemm_kernel(const float* __restrict__ bias,
                                                      float* __restrict__ out) {
    extern __shared__ __align__(16) char smem[];
    const uint32_t sb = smem_u32(smem);
    const int tid  = threadIdx.x;
    const int warp = tid >> 5, lane = tid & 31;
    const int wm = warp >> 1, wn = warp & 1;
    const int m0 = blockIdx.y * BM, n0 = blockIdx.x * BN;

    // per-CTA epilogue tables
    float* s_sw = (float*)(smem + OFF_TAB);
    int*   s_rs = (int*)(smem + OFF_TAB + 512);
    float* s_bi = (float*)(smem + OFF_TAB + 1024);
    if (tid < 128) {
        s_sw[tid] = g_wscale[n0 + tid];
        s_rs[tid] = g_wrowsum[n0 + tid];
        s_bi[tid] = bias[n0 + tid];
    }

    const char* Ag = (const char*)g_Xq + (size_t)m0 * K_DIM;
    const char* Bg = (const char*)g_Wq + (size_t)n0 * K_DIM;

    // stage loader: 512 16B chunks for A + 512 for B; 2 of each per thread
    const int lrow = tid >> 2, lch = tid & 3;   // thread's (row, chunk) pattern
#define LOAD_STAGE(s, k) do {                                                    \
        uint32_t ab = sb + (s) * STAGE_BYTES;                                    \
        uint32_t bb = ab + TILE_BYTES;                                           \
        const char* ag = Ag + (size_t)(k) * BKB;                                 \
        const char* bg = Bg + (size_t)(k) * BKB;                                 \
        _Pragma("unroll")                                                        \
        for (int it = 0; it < 2; it++) {                                         \
            int row = lrow + it * 64;                                            \
            cp_async16(ab + row * ROWSTR + lch * 16, ag + (size_t)row * K_DIM + lch * 16); \
            cp_async16(bb + row * ROWSTR + lch * 16, bg + (size_t)row * K_DIM + lch * 16); \
        }                                                                        \
    } while (0)

    LOAD_STAGE(0, 0); CP_COMMIT();
    LOAD_STAGE(1, 1); CP_COMMIT();

    int acc[2][8][4];
#pragma unroll
    for (int i = 0; i < 2; i++)
#pragma unroll
        for (int j = 0; j < 8; j++)
#pragma unroll
            for (int c = 0; c < 4; c++) acc[i][j][c] = 0;

    const int mi = lane >> 3, l7 = lane & 7;

    for (int k = 0; k < KIT; k++) {
        const int s = k % NSTG;
        CP_WAIT1();
        __syncthreads();
        if (k + 2 < KIT) LOAD_STAGE((k + 2) % NSTG, k + 2);
        CP_COMMIT();

        const uint32_t abase = sb + s * STAGE_BYTES + (wm * 32) * ROWSTR;
        const uint32_t bbase = sb + s * STAGE_BYTES + TILE_BYTES + (wn * 64) * ROWSTR;

#pragma unroll
        for (int ks = 0; ks < 2; ks++) {
            uint32_t a[2][4], b0[8], b1[8];
#pragma unroll
            for (int i = 0; i < 2; i++) {
                // M0: rows+0 cc; M1: rows+8 cc; M2: rows+0 cc+1; M3: rows+8 cc+1
                int row = i * 16 + (mi & 1) * 8 + l7;
                int cc  = ks * 2 + (mi >> 1);
                ldsm_x4(abase + row * ROWSTR + cc * 16, a[i][0], a[i][1], a[i][2], a[i][3]);
            }
#pragma unroll
            for (int jp = 0; jp < 4; jp++) {
                // M0: tile 2jp cc; M1: tile 2jp cc+1; M2: tile 2jp+1 cc; M3: tile 2jp+1 cc+1
                int row = jp * 16 + (mi >> 1) * 8 + l7;
                int cc  = ks * 2 + (mi & 1);
                uint32_t r0, r1, r2, r3;
                ldsm_x4(bbase + row * ROWSTR + cc * 16, r0, r1, r2, r3);
                b0[2 * jp] = r0; b1[2 * jp] = r1;
                b0[2 * jp + 1] = r2; b1[2 * jp + 1] = r3;
            }
#pragma unroll
            for (int i = 0; i < 2; i++)
#pragma unroll
                for (int j = 0; j < 8; j++) {
                    uint32_t bb[2] = { b0[j], b1[j] };
                    mma_u8s8(acc[i][j], a[i], bb);
                }
        }
    }
    __syncthreads();

    // ---------------- epilogue: exact int zp-correction + f32 dequant ----------------
    const int g  = lane >> 2;          // group row
    const int cl = (lane & 3) * 2;     // col pair base
    float sa[2][2]; int zp[2][2]; int grow[2][2];
#pragma unroll
    for (int i = 0; i < 2; i++)
#pragma unroll
        for (int h = 0; h < 2; h++) {
            int r = m0 + wm * 32 + i * 16 + h * 8 + g;
            grow[i][h] = r;
            sa[i][h] = g_ascale[r];
            zp[i][h] = g_azp[r];
        }

#pragma unroll
    for (int i = 0; i < 2; i++)
#pragma unroll
        for (int j = 0; j < 8; j++) {
            const int lc = wn * 64 + j * 8 + cl;
            const int rs0 = s_rs[lc], rs1 = s_rs[lc + 1];
            const float sw0 = s_sw[lc], sw1 = s_sw[lc + 1];
            const float bi0 = s_bi[lc], bi1 = s_bi[lc + 1];
#pragma unroll
            for (int h = 0; h < 2; h++) {
                const float s0 = sa[i][h];
                const int   z  = zp[i][h];
                float2 v;
                v.x = (float)(acc[i][j][h * 2 + 0] - z * rs0) * (s0 * sw0) + bi0;
                v.y = (float)(acc[i][j][h * 2 + 1] - z * rs1) * (s0 * sw1) + bi1;
                *(float2*)(out + (size_t)grow[i][h] * N_DIM + n0 + lc) = v;
            }
        }
#undef LOAD_STAGE
}

// ---------------- launch ----------------
extern "C" void kernel_launch(void* const* d_in, const int* in_sizes, int n_in,
                              void* d_out, int out_size) {
    const float* x    = (const float*)d_in[0];
    const float* w    = (const float*)d_in[1];
    const float* bias = (const float*)d_in[2];
    float* out = (float*)d_out;

    cudaFuncSetAttribute(gemm_kernel, cudaFuncAttributeMaxDynamicSharedMemorySize, SMEM_TOTAL);

    wq_kernel<<<N_DIM, 256>>>(w);
    xq_kernel<<<M_DIM, 256>>>(x);
    gemm_kernel<<<dim3(N_DIM / BN, M_DIM / BM), 256, SMEM_TOTAL>>>(bias, out);
}

// round 10
// speedup vs baseline: 2.8129x; 2.5843x over previous
#include <cuda_runtime.h>
#include <cuda_fp16.h>
#include <cstdint>

#define K_DIM 4096
#define M_DIM 8192
#define N_DIM 4096

// GEMM tiling: BM=128, BN=256, BK=64 halfs (128B rows), 512 threads (4x4 warps)
#define BM 128
#define BN 256
#define KIT 64                     // K / 64
#define A_TILE 16384               // 128 rows x 128B
#define B_TILE 32768               // 256 rows x 128B
#define STAGE_BYTES (A_TILE + B_TILE)
#define NSTG 3
#define OFF_TAB (NSTG * STAGE_BYTES)
#define SMEM_TOTAL (OFF_TAB + 256 * 8)

// ---------------- scratch (allocation-free) ----------------
__device__ __align__(16) __half g_Wh[(size_t)N_DIM * K_DIM];  // 32MB [N][K]
__device__ __align__(16) __half g_Xh[(size_t)M_DIM * K_DIM];  // 64MB [M][K], holds (Xq - zp)
__device__ float g_wscale[N_DIM];
__device__ float g_ascale[M_DIM];

// ---------------- PTX helpers (base-target safe) ----------------
__device__ __forceinline__ uint32_t smem_u32(const void* p) {
    uint32_t a;
    asm("{ .reg .u64 t; cvta.to.shared.u64 t, %1; cvt.u32.u64 %0, t; }" : "=r"(a) : "l"(p));
    return a;
}
__device__ __forceinline__ void cp_async16(uint32_t dst, const void* src) {
    asm volatile("cp.async.cg.shared.global [%0], [%1], 16;" :: "r"(dst), "l"(src));
}
#define CP_COMMIT() asm volatile("cp.async.commit_group;" ::: "memory")
#define CP_WAIT1()  asm volatile("cp.async.wait_group 1;" ::: "memory")

__device__ __forceinline__ void ldsm_x4(uint32_t addr, uint32_t& r0, uint32_t& r1,
                                        uint32_t& r2, uint32_t& r3) {
    asm volatile("ldmatrix.sync.aligned.m8n8.x4.shared.b16 {%0,%1,%2,%3}, [%4];"
                 : "=r"(r0), "=r"(r1), "=r"(r2), "=r"(r3) : "r"(addr));
}
__device__ __forceinline__ void mma_f16(float* c, const uint32_t* a, uint32_t b0, uint32_t b1) {
    asm volatile("mma.sync.aligned.m16n8k16.row.col.f32.f16.f16.f32 "
                 "{%0,%1,%2,%3}, {%4,%5,%6,%7}, {%8,%9}, {%0,%1,%2,%3};"
                 : "+f"(c[0]), "+f"(c[1]), "+f"(c[2]), "+f"(c[3])
                 : "r"(a[0]), "r"(a[1]), "r"(a[2]), "r"(a[3]), "r"(b0), "r"(b1));
}

// ---------------- weight quantization: one block per output row n ----------------
__global__ __launch_bounds__(256) void wq_kernel(const float* __restrict__ W) {
    const int n = blockIdx.x;
    const int t = threadIdx.x, wid = t >> 5, lid = t & 31;
    const float* row = W + (size_t)n * K_DIM;

    float4 v[4];
#pragma unroll
    for (int i = 0; i < 4; i++) v[i] = *(const float4*)(row + t * 16 + i * 4);

    float amax = 0.f;
#pragma unroll
    for (int i = 0; i < 4; i++)
        amax = fmaxf(amax, fmaxf(fmaxf(fabsf(v[i].x), fabsf(v[i].y)),
                                 fmaxf(fabsf(v[i].z), fabsf(v[i].w))));
#pragma unroll
    for (int o = 16; o > 0; o >>= 1)
        amax = fmaxf(amax, __shfl_xor_sync(0xffffffffu, amax, o));

    __shared__ float smx[8];
    if (lid == 0) smx[wid] = amax;
    __syncthreads();
    float gmax = smx[0];
#pragma unroll
    for (int i = 1; i < 8; i++) gmax = fmaxf(gmax, smx[i]);
    const float scale = (gmax > 0.f) ? gmax / 127.0f : 1.0f;
    if (t == 0) g_wscale[n] = scale;

    __half2 h[8];
#pragma unroll
    for (int i = 0; i < 4; i++) {
        float q0 = fminf(fmaxf(rintf(v[i].x / scale), -127.f), 127.f);
        float q1 = fminf(fmaxf(rintf(v[i].y / scale), -127.f), 127.f);
        float q2 = fminf(fmaxf(rintf(v[i].z / scale), -127.f), 127.f);
        float q3 = fminf(fmaxf(rintf(v[i].w / scale), -127.f), 127.f);
        h[2 * i]     = __floats2half2_rn(q0, q1);
        h[2 * i + 1] = __floats2half2_rn(q2, q3);
    }
    int4* dst = (int4*)(g_Wh + (size_t)n * K_DIM + t * 16);
    dst[0] = *(int4*)&h[0];
    dst[1] = *(int4*)&h[4];
}

// ---------------- activation quantization: one block per token m ----------------
// stores (Xq - zp) directly as fp16 -> no zero-point correction in GEMM
__global__ __launch_bounds__(256) void xq_kernel(const float* __restrict__ X) {
    const int m = blockIdx.x;
    const int t = threadIdx.x, wid = t >> 5, lid = t & 31;
    const float* row = X + (size_t)m * K_DIM;

    float4 v[4];
#pragma unroll
    for (int i = 0; i < 4; i++) v[i] = *(const float4*)(row + t * 16 + i * 4);

    float lmin = v[0].x, lmax = v[0].x;
#pragma unroll
    for (int i = 0; i < 4; i++) {
        lmin = fminf(lmin, fminf(fminf(v[i].x, v[i].y), fminf(v[i].z, v[i].w)));
        lmax = fmaxf(lmax, fmaxf(fmaxf(v[i].x, v[i].y), fmaxf(v[i].z, v[i].w)));
    }
#pragma unroll
    for (int o = 16; o > 0; o >>= 1) {
        lmin = fminf(lmin, __shfl_xor_sync(0xffffffffu, lmin, o));
        lmax = fmaxf(lmax, __shfl_xor_sync(0xffffffffu, lmax, o));
    }
    __shared__ float smn[8], smx[8];
    if (lid == 0) { smn[wid] = lmin; smx[wid] = lmax; }
    __syncthreads();
    float gmin = smn[0], gmax = smx[0];
#pragma unroll
    for (int i = 1; i < 8; i++) { gmin = fminf(gmin, smn[i]); gmax = fmaxf(gmax, smx[i]); }

    const float rng   = gmax - gmin;
    const float scale = (rng > 0.f) ? rng / 255.0f : 1.0f;
    const float zp    = rintf(-gmin / scale);
    if (t == 0) g_ascale[m] = scale;

    __half2 h[8];
#pragma unroll
    for (int i = 0; i < 4; i++) {
        float q0 = fminf(fmaxf(rintf(v[i].x / scale) + zp, 0.f), 255.f) - zp;
        float q1 = fminf(fmaxf(rintf(v[i].y / scale) + zp, 0.f), 255.f) - zp;
        float q2 = fminf(fmaxf(rintf(v[i].z / scale) + zp, 0.f), 255.f) - zp;
        float q3 = fminf(fmaxf(rintf(v[i].w / scale) + zp, 0.f), 255.f) - zp;
        h[2 * i]     = __floats2half2_rn(q0, q1);
        h[2 * i + 1] = __floats2half2_rn(q2, q3);
    }
    int4* dst = (int4*)(g_Xh + (size_t)m * K_DIM + t * 16);
    dst[0] = *(int4*)&h[0];
    dst[1] = *(int4*)&h[4];
}

// ---------------- fp16 tensor-core GEMM ----------------
// 128x256 tile, BK=64 halfs (128B), 3-stage cp.async, 16 warps (4m x 4n), warp tile 32x64.
// SMEM rows 128B with XOR-8 chunk swizzle: phys_chunk = chunk ^ (row & 7).
__global__ __launch_bounds__(512, 1) void gemm_kernel(const float* __restrict__ bias,
                                                      float* __restrict__ out) {
    extern __shared__ __align__(16) char smem[];
    const uint32_t sb = smem_u32(smem);
    const int tid  = threadIdx.x;
    const int warp = tid >> 5, lane = tid & 31;
    const int wm = warp >> 2, wn = warp & 3;
    const int m0 = blockIdx.y * BM, n0 = blockIdx.x * BN;

    float* s_sw = (float*)(smem + OFF_TAB);
    float* s_bi = (float*)(smem + OFF_TAB + 1024);
    if (tid < 256) {
        s_sw[tid] = g_wscale[n0 + tid];
        s_bi[tid] = bias[n0 + tid];
    }

    const char* Ag = (const char*)g_Xh + (size_t)m0 * K_DIM * 2;
    const char* Bg = (const char*)g_Wh + (size_t)n0 * K_DIM * 2;

#define LOAD_STAGE(s, k) do {                                                      \
        uint32_t ab = sb + (s) * STAGE_BYTES;                                      \
        uint32_t bb = ab + A_TILE;                                                 \
        const char* ag = Ag + (size_t)(k) * 128;                                   \
        const char* bg = Bg + (size_t)(k) * 128;                                   \
        _Pragma("unroll")                                                          \
        for (int it = 0; it < 2; it++) {                                           \
            int idx = tid + it * 512, row = idx >> 3, ch = idx & 7;                \
            cp_async16(ab + row * 128 + ((ch ^ (row & 7)) * 16),                   \
                       ag + (size_t)row * (K_DIM * 2) + ch * 16);                  \
        }                                                                          \
        _Pragma("unroll")                                                          \
        for (int it = 0; it < 4; it++) {                                           \
            int idx = tid + it * 512, row = idx >> 3, ch = idx & 7;                \
            cp_async16(bb + row * 128 + ((ch ^ (row & 7)) * 16),                   \
                       bg + (size_t)row * (K_DIM * 2) + ch * 16);                  \
        }                                                                          \
    } while (0)

    LOAD_STAGE(0, 0); CP_COMMIT();
    LOAD_STAGE(1, 1); CP_COMMIT();

    float acc[2][8][4];
#pragma unroll
    for (int i = 0; i < 2; i++)
#pragma unroll
        for (int j = 0; j < 8; j++)
#pragma unroll
            for (int c = 0; c < 4; c++) acc[i][j][c] = 0.f;

    const int lrow = lane & 15;          // row-in-16 for ldmatrix
    const int lhi  = lane >> 4;          // chunk selector (0/1)

    for (int k = 0; k < KIT; k++) {
        const int s = k % NSTG;
        CP_WAIT1();
        __syncthreads();
        if (k + 2 < KIT) LOAD_STAGE((k + 2) % NSTG, k + 2);
        CP_COMMIT();

        const uint32_t abase = sb + s * STAGE_BYTES;
        const uint32_t bbase = abase + A_TILE;

#pragma unroll
        for (int ks = 0; ks < 4; ks++) {
            const int cbase = 2 * ks + lhi;
            uint32_t a[2][4], bl[8], bh[8];
#pragma unroll
            for (int i = 0; i < 2; i++) {
                int row = wm * 32 + i * 16 + lrow;
                ldsm_x4(abase + row * 128 + ((cbase ^ (row & 7)) * 16),
                        a[i][0], a[i][1], a[i][2], a[i][3]);
            }
#pragma unroll
            for (int jp = 0; jp < 4; jp++) {
                int row = wn * 64 + jp * 16 + lrow;
                uint32_t r0, r1, r2, r3;
                ldsm_x4(bbase + row * 128 + ((cbase ^ (row & 7)) * 16), r0, r1, r2, r3);
                bl[2 * jp] = r0;     bh[2 * jp] = r2;      // n-tile low:  chunks (c, c+1)
                bl[2 * jp + 1] = r1; bh[2 * jp + 1] = r3;  // n-tile high
            }
#pragma unroll
            for (int i = 0; i < 2; i++)
#pragma unroll
                for (int j = 0; j < 8; j++)
                    mma_f16(acc[i][j], a[i], bl[j], bh[j]);
        }
    }
    __syncthreads();

    // ---------------- epilogue: Y = acc * (sa*sw) + bias ----------------
    const int g  = lane >> 2;
    const int cl = (lane & 3) * 2;
    float sa[2][2]; int grow[2][2];
#pragma unroll
    for (int i = 0; i < 2; i++)
#pragma unroll
        for (int h = 0; h < 2; h++) {
            int r = m0 + wm * 32 + i * 16 + h * 8 + g;
            grow[i][h] = r;
            sa[i][h] = g_ascale[r];
        }

#pragma unroll
    for (int i = 0; i < 2; i++)
#pragma unroll
        for (int j = 0; j < 8; j++) {
            const int lc = wn * 64 + j * 8 + cl;
            const float sw0 = s_sw[lc], sw1 = s_sw[lc + 1];
            const float bi0 = s_bi[lc], bi1 = s_bi[lc + 1];
#pragma unroll
            for (int h = 0; h < 2; h++) {
                const float s0 = sa[i][h];
                float2 v;
                v.x = acc[i][j][h * 2 + 0] * (s0 * sw0) + bi0;
                v.y = acc[i][j][h * 2 + 1] * (s0 * sw1) + bi1;
                *(float2*)(out + (size_t)grow[i][h] * N_DIM + n0 + lc) = v;
            }
        }
#undef LOAD_STAGE
}

// ---------------- launch ----------------
extern "C" void kernel_launch(void* const* d_in, const int* in_sizes, int n_in,
                              void* d_out, int out_size) {
    const float* x    = (const float*)d_in[0];
    const float* w    = (const float*)d_in[1];
    const float* bias = (const float*)d_in[2];
    float* out = (float*)d_out;

    cudaFuncSetAttribute(gemm_kernel, cudaFuncAttributeMaxDynamicSharedMemorySize, SMEM_TOTAL);

    wq_kernel<<<N_DIM, 256>>>(w);
    xq_kernel<<<M_DIM, 256>>>(x);
    gemm_kernel<<<dim3(N_DIM / BN, M_DIM / BM), 512, SMEM_TOTAL>>>(bias, out);
}